// round 2
// baseline (speedup 1.0000x reference)
#include <cuda_runtime.h>
#include <cstdint>

#define BM 64
#define BN 64
#define HD 64
#define SEQ 2048
#define NH 12
#define NB 4

constexpr int KS_STRIDE = 68;  // uints per row (pad -> conflict-free QK B-frag LDS)
constexpr int VS_STRIDE = 72;  // pad -> conflict-free PV B-frag LDS
constexpr int PS_STRIDE = 68;  // pad -> conflict-free PV A-frag LDS
constexpr int SMEM_UINTS = 64 * KS_STRIDE + 64 * VS_STRIDE + 64 * PS_STRIDE;
constexpr int SMEM_BYTES = SMEM_UINTS * 4;  // 53248

__device__ __forceinline__ unsigned f2tf(float f) {
    unsigned u;
    asm("cvt.rna.tf32.f32 %0, %1;" : "=r"(u) : "f"(f));
    return u;
}

__device__ __forceinline__ void mma_m16n8k8(float* c, const unsigned* a, const unsigned* b) {
    asm volatile(
        "mma.sync.aligned.m16n8k8.row.col.f32.tf32.tf32.f32 "
        "{%0,%1,%2,%3}, {%4,%5,%6,%7}, {%8,%9}, {%0,%1,%2,%3};"
        : "+f"(c[0]), "+f"(c[1]), "+f"(c[2]), "+f"(c[3])
        : "r"(a[0]), "r"(a[1]), "r"(a[2]), "r"(a[3]), "r"(b[0]), "r"(b[1]));
}

extern "C" __global__ void __launch_bounds__(128, 2)
fa2_tf32_kernel(const float* __restrict__ q, const float* __restrict__ k,
                const float* __restrict__ v, const float* __restrict__ bias,
                float* __restrict__ out) {
    extern __shared__ unsigned smem[];
    unsigned* Ks = smem;                       // [64][KS_STRIDE] tf32 bits, K[key][d]
    unsigned* Vs = Ks + 64 * KS_STRIDE;        // [64][VS_STRIDE] tf32 bits, V[key][d]
    unsigned* Ps = Vs + 64 * VS_STRIDE;        // [64][PS_STRIDE] tf32 bits, P[qrow][key]

    const int tid  = threadIdx.x;
    const int warp = tid >> 5;
    const int lane = tid & 31;
    const int r  = lane >> 2;   // groupID (row within fragment)
    const int cq = lane & 3;    // threadID in group

    const int h = blockIdx.y;
    const int b = blockIdx.z;
    const int q0 = blockIdx.x * BM;

    const int row0 = q0 + warp * 16 + r;       // first query row of this thread
    // row1 = row0 + 8

    const int rowstride = NH * HD;             // 768 floats between sequence positions
    const float* qrow0 = q + (size_t)(b * SEQ + row0) * rowstride + (size_t)h * HD;
    const float* qrow1 = qrow0 + (size_t)8 * rowstride;
    const float* kbase = k + (size_t)b * SEQ * rowstride + (size_t)h * HD;
    const float* vbase = v + (size_t)b * SEQ * rowstride + (size_t)h * HD;
    const float* bias0 = bias + ((size_t)(b * NH + h)) * SEQ * SEQ + (size_t)row0 * SEQ;
    const float* bias1 = bias0 + (size_t)8 * SEQ;

    // ---- Q fragments (A-layout, tf32), resident in registers for whole kernel ----
    unsigned qa[8][4];
#pragma unroll
    for (int kk = 0; kk < 8; kk++) {
        qa[kk][0] = f2tf(__ldg(&qrow0[kk * 8 + cq]));
        qa[kk][1] = f2tf(__ldg(&qrow1[kk * 8 + cq]));
        qa[kk][2] = f2tf(__ldg(&qrow0[kk * 8 + cq + 4]));
        qa[kk][3] = f2tf(__ldg(&qrow1[kk * 8 + cq + 4]));
    }

    float o[8][4];
#pragma unroll
    for (int n = 0; n < 8; n++) {
        o[n][0] = 0.f; o[n][1] = 0.f; o[n][2] = 0.f; o[n][3] = 0.f;
    }
    float m0 = -1e30f, m1 = -1e30f, l0 = 0.f, l1 = 0.f;

    const float scale = 0.125f;  // 1/sqrt(64)

    unsigned* prow0 = &Ps[(warp * 16 + r) * PS_STRIDE];
    unsigned* prow1 = prow0 + 8 * PS_STRIDE;

    for (int kt = 0; kt < SEQ / BN; kt++) {
        __syncthreads();
        // ---- stage K,V tile (64 keys x 64 d) into smem, converted to tf32 ----
        const float* ksrc = kbase + (size_t)(kt * BN) * rowstride;
        const float* vsrc = vbase + (size_t)(kt * BN) * rowstride;
#pragma unroll
        for (int i = 0; i < 8; i++) {
            int idx = tid + i * 128;       // 0..1023
            int row = idx >> 4;
            int c4  = (idx & 15) << 2;
            float4 k4 = *(const float4*)(ksrc + (size_t)row * rowstride + c4);
            uint4 ku = { f2tf(k4.x), f2tf(k4.y), f2tf(k4.z), f2tf(k4.w) };
            *(uint4*)&Ks[row * KS_STRIDE + c4] = ku;
            float4 v4 = *(const float4*)(vsrc + (size_t)row * rowstride + c4);
            uint4 vu = { f2tf(v4.x), f2tf(v4.y), f2tf(v4.z), f2tf(v4.w) };
            *(uint4*)&Vs[row * VS_STRIDE + c4] = vu;
        }
        __syncthreads();

        // ---- S = Q K^T (each warp: 16x64 scores) ----
        float s[8][4];
#pragma unroll
        for (int n = 0; n < 8; n++) {
            s[n][0] = 0.f; s[n][1] = 0.f; s[n][2] = 0.f; s[n][3] = 0.f;
#pragma unroll
            for (int kk = 0; kk < 8; kk++) {
                unsigned bf[2];
                const unsigned* krow = &Ks[(n * 8 + r) * KS_STRIDE + kk * 8];
                bf[0] = krow[cq];
                bf[1] = krow[cq + 4];
                mma_m16n8k8(s[n], qa[kk], bf);
            }
        }

        // ---- scale + bias (bias loaded directly in C-fragment layout) ----
        const int kc = kt * BN;
#pragma unroll
        for (int n = 0; n < 8; n++) {
            float2 bb0 = *(const float2*)(bias0 + kc + n * 8 + 2 * cq);
            float2 bb1 = *(const float2*)(bias1 + kc + n * 8 + 2 * cq);
            s[n][0] = fmaf(s[n][0], scale, bb0.x);
            s[n][1] = fmaf(s[n][1], scale, bb0.y);
            s[n][2] = fmaf(s[n][2], scale, bb1.x);
            s[n][3] = fmaf(s[n][3], scale, bb1.y);
        }

        // ---- online softmax (rows row0 / row0+8) ----
        float mx0 = s[0][0], mx1 = s[0][2];
#pragma unroll
        for (int n = 0; n < 8; n++) {
            mx0 = fmaxf(mx0, fmaxf(s[n][0], s[n][1]));
            mx1 = fmaxf(mx1, fmaxf(s[n][2], s[n][3]));
        }
        mx0 = fmaxf(mx0, __shfl_xor_sync(0xffffffffu, mx0, 1));
        mx0 = fmaxf(mx0, __shfl_xor_sync(0xffffffffu, mx0, 2));
        mx1 = fmaxf(mx1, __shfl_xor_sync(0xffffffffu, mx1, 1));
        mx1 = fmaxf(mx1, __shfl_xor_sync(0xffffffffu, mx1, 2));

        float mn0 = fmaxf(m0, mx0), mn1 = fmaxf(m1, mx1);
        float a0 = __expf(m0 - mn0), a1 = __expf(m1 - mn1);
        m0 = mn0; m1 = mn1;

        float sm0 = 0.f, sm1 = 0.f;
#pragma unroll
        for (int n = 0; n < 8; n++) {
            s[n][0] = __expf(s[n][0] - mn0);
            s[n][1] = __expf(s[n][1] - mn0);
            s[n][2] = __expf(s[n][2] - mn1);
            s[n][3] = __expf(s[n][3] - mn1);
            sm0 += s[n][0] + s[n][1];
            sm1 += s[n][2] + s[n][3];
            o[n][0] *= a0; o[n][1] *= a0; o[n][2] *= a1; o[n][3] *= a1;
        }
        sm0 += __shfl_xor_sync(0xffffffffu, sm0, 1);
        sm0 += __shfl_xor_sync(0xffffffffu, sm0, 2);
        sm1 += __shfl_xor_sync(0xffffffffu, sm1, 1);
        sm1 += __shfl_xor_sync(0xffffffffu, sm1, 2);
        l0 = l0 * a0 + sm0;
        l1 = l1 * a1 + sm1;

        // ---- stage P (tf32) to warp-private smem (C-frag -> A-frag relayout) ----
#pragma unroll
        for (int n = 0; n < 8; n++) {
            uint2 p0 = { f2tf(s[n][0]), f2tf(s[n][1]) };
            *(uint2*)&prow0[n * 8 + 2 * cq] = p0;
            uint2 p1 = { f2tf(s[n][2]), f2tf(s[n][3]) };
            *(uint2*)&prow1[n * 8 + 2 * cq] = p1;
        }
        __syncwarp();

        // ---- O += P V ----
#pragma unroll
        for (int kk = 0; kk < 8; kk++) {
            unsigned pa[4];
            pa[0] = prow0[kk * 8 + cq];
            pa[1] = prow1[kk * 8 + cq];
            pa[2] = prow0[kk * 8 + cq + 4];
            pa[3] = prow1[kk * 8 + cq + 4];
#pragma unroll
            for (int n = 0; n < 8; n++) {
                unsigned bf[2];
                bf[0] = Vs[(kk * 8 + cq) * VS_STRIDE + n * 8 + r];
                bf[1] = Vs[(kk * 8 + cq + 4) * VS_STRIDE + n * 8 + r];
                mma_m16n8k8(o[n], pa, bf);
            }
        }
    }

    // ---- epilogue: normalize and store ----
    float inv0 = 1.f / l0, inv1 = 1.f / l1;
    float* orow0 = out + (size_t)(b * SEQ + row0) * rowstride + (size_t)h * HD;
    float* orow1 = orow0 + (size_t)8 * rowstride;
#pragma unroll
    for (int n = 0; n < 8; n++) {
        float2 t0 = { o[n][0] * inv0, o[n][1] * inv0 };
        *(float2*)&orow0[n * 8 + 2 * cq] = t0;
        float2 t1 = { o[n][2] * inv1, o[n][3] * inv1 };
        *(float2*)&orow1[n * 8 + 2 * cq] = t1;
    }
}

extern "C" void kernel_launch(void* const* d_in, const int* in_sizes, int n_in,
                              void* d_out, int out_size) {
    const float* q    = (const float*)d_in[0];
    const float* k    = (const float*)d_in[1];
    const float* v    = (const float*)d_in[2];
    const float* bias = (const float*)d_in[3];
    float* out = (float*)d_out;

    cudaFuncSetAttribute(fa2_tf32_kernel,
                         cudaFuncAttributeMaxDynamicSharedMemorySize, SMEM_BYTES);

    dim3 grid(SEQ / BM, NH, NB);
    fa2_tf32_kernel<<<grid, 128, SMEM_BYTES>>>(q, k, v, bias, out);
}